// round 4
// baseline (speedup 1.0000x reference)
#include <cuda_runtime.h>
#include <cstdint>

// ---------------------------------------------------------------------------
// ChamferLoss: loss = ( sum_i min_j ||o_i - t_j|| + sum_j min_i ||t_j - o_i|| ) / 1000
// Norm-expansion: ||a-b||^2 = sq_a + ( (-2b)·a + sq_b )
// Inner loop uses packed FFMA2 (fma.rn.f32x2): 1.5 fma-issues + 1 FMNMX / pair.
// ---------------------------------------------------------------------------

#define NMAX  16384
#define BLOCK 128
#define APT   8            // query points per thread (4 packed groups)
#define SPLIT 32           // ref-set slices per direction
#define SLICE (NMAX / SPLIT)   // 512 ref points; 512*32B = 16KB shared

typedef unsigned long long ull;

// scratch (no allocations allowed)
__device__ float4     g_query[2][NMAX];   // (x, y, z, sq)
__device__ ulonglong4 g_ref2[2][NMAX];    // packed duplicated: (xx, yy, zz, ss), x=-2x etc.
__device__ unsigned   g_min[2][NMAX];     // per-point min sq-dist (uint-ordered floats)

__device__ __forceinline__ ull pack2(float a, float b) {
    return (ull)__float_as_uint(a) | ((ull)__float_as_uint(b) << 32);
}

// ---------------------------------------------------------------------------
__global__ void prep_kernel(const float* __restrict__ tgt,
                            const float* __restrict__ outp,
                            int n, int m, float* out) {
    int i = blockIdx.x * blockDim.x + threadIdx.x;
    if (i == 0) *out = 0.0f;
    if (i < n) {
        float x = tgt[3 * i], y = tgt[3 * i + 1], z = tgt[3 * i + 2];
        float sq = fmaf(x, x, fmaf(y, y, z * z));
        g_query[0][i] = make_float4(x, y, z, sq);
        float tx = -2.0f * x, ty = -2.0f * y, tz = -2.0f * z;
        g_ref2[0][i] = make_ulonglong4(pack2(tx, tx), pack2(ty, ty),
                                       pack2(tz, tz), pack2(sq, sq));
        g_min[0][i] = 0x7F800000u;  // +inf
    }
    if (i < m) {
        float x = outp[3 * i], y = outp[3 * i + 1], z = outp[3 * i + 2];
        float sq = fmaf(x, x, fmaf(y, y, z * z));
        g_query[1][i] = make_float4(x, y, z, sq);
        float tx = -2.0f * x, ty = -2.0f * y, tz = -2.0f * z;
        g_ref2[1][i] = make_ulonglong4(pack2(tx, tx), pack2(ty, ty),
                                       pack2(tz, tz), pack2(sq, sq));
        g_min[1][i] = 0x7F800000u;
    }
}

// ---------------------------------------------------------------------------
// blockIdx.z = dir. dir 0: query=target(set0), ref=output(set1) -> g_min[0]
//                   dir 1: query=output(set1), ref=target(set0) -> g_min[1]
__global__ __launch_bounds__(BLOCK) void min_kernel(int n, int m) {
    __shared__ ulonglong4 sh[SLICE];

    const int dir  = blockIdx.z;
    const int qset = dir;
    const int rset = 1 - dir;
    const int qn = (qset == 0) ? n : m;
    const int rn = (rset == 0) ? n : m;

    // stage this block's ref slice (pre-duplicated packed broadcasts)
    const int rbase = blockIdx.y * SLICE;
    const int L = min(SLICE, rn - rbase);
    for (int j = threadIdx.x; j < L; j += BLOCK)
        sh[j] = g_ref2[rset][rbase + j];
    __syncthreads();

    // load APT query points; pack consecutive pairs into f32x2 registers
    const int qbase = blockIdx.x * (BLOCK * APT);
    ull ax2[APT / 2], ay2[APT / 2], az2[APT / 2];
    float sqa[APT], tmin[APT];
    int qidx[APT];
    float qx[APT], qy[APT], qz[APT];
    #pragma unroll
    for (int k = 0; k < APT; k++) {
        int idx = qbase + threadIdx.x + k * BLOCK;
        qidx[k] = idx;
        float4 q = (idx < qn) ? g_query[qset][idx] : make_float4(0.f, 0.f, 0.f, 0.f);
        qx[k] = q.x; qy[k] = q.y; qz[k] = q.z; sqa[k] = q.w;
        tmin[k] = __uint_as_float(0x7F800000u);
    }
    #pragma unroll
    for (int k = 0; k < APT / 2; k++) {
        ax2[k] = pack2(qx[2 * k], qx[2 * k + 1]);
        ay2[k] = pack2(qy[2 * k], qy[2 * k + 1]);
        az2[k] = pack2(qz[2 * k], qz[2 * k + 1]);
    }

    // main loop: per ref point j, per packed pair: 3 FFMA2 + 2 FMNMX
    #pragma unroll 2
    for (int j = 0; j < L; j++) {
        ulonglong4 b = sh[j];   // 2x LDS.128 broadcast
        #pragma unroll
        for (int k = 0; k < APT / 2; k++) {
            ull t;
            asm("fma.rn.f32x2 %0, %1, %2, %3;" : "=l"(t) : "l"(az2[k]), "l"(b.z), "l"(b.w));
            asm("fma.rn.f32x2 %0, %1, %2, %3;" : "=l"(t) : "l"(ay2[k]), "l"(b.y), "l"(t));
            asm("fma.rn.f32x2 %0, %1, %2, %3;" : "=l"(t) : "l"(ax2[k]), "l"(b.x), "l"(t));
            float lo, hi;
            asm("mov.b64 {%0, %1}, %2;" : "=f"(lo), "=f"(hi) : "l"(t));
            tmin[2 * k]     = fminf(tmin[2 * k], lo);
            tmin[2 * k + 1] = fminf(tmin[2 * k + 1], hi);
        }
    }

    // publish slice-local mins (non-negative floats order as uints)
    #pragma unroll
    for (int k = 0; k < APT; k++) {
        if (qidx[k] < qn) {
            float v = fmaxf(sqa[k] + tmin[k], 0.0f);
            atomicMin(&g_min[qset][qidx[k]], __float_as_uint(v));
        }
    }
}

// ---------------------------------------------------------------------------
__global__ void reduce_kernel(int n, int m, float* out) {
    __shared__ float warp_sums[8];
    const int total = n + m;
    float s = 0.0f;
    for (int i = blockIdx.x * blockDim.x + threadIdx.x; i < total;
         i += gridDim.x * blockDim.x) {
        unsigned u = (i < n) ? g_min[0][i] : g_min[1][i - n];
        s += sqrtf(__uint_as_float(u));
    }
    #pragma unroll
    for (int o = 16; o > 0; o >>= 1)
        s += __shfl_down_sync(0xFFFFFFFFu, s, o);
    int lane = threadIdx.x & 31, wid = threadIdx.x >> 5;
    if (lane == 0) warp_sums[wid] = s;
    __syncthreads();
    if (wid == 0) {
        s = (lane < (int)(blockDim.x / 32)) ? warp_sums[lane] : 0.0f;
        #pragma unroll
        for (int o = 16; o > 0; o >>= 1)
            s += __shfl_down_sync(0xFFFFFFFFu, s, o);
        if (lane == 0) atomicAdd(out, s * 1.0e-3f);
    }
}

// ---------------------------------------------------------------------------
extern "C" void kernel_launch(void* const* d_in, const int* in_sizes, int n_in,
                              void* d_out, int out_size) {
    const float* target = (const float*)d_in[0];
    const float* output = (const float*)d_in[1];
    const int n = in_sizes[0] / 3;
    const int m = in_sizes[1] / 3;
    float* out = (float*)d_out;

    int pmax = max(n, m);
    prep_kernel<<<(pmax + 255) / 256, 256>>>(target, output, n, m, out);

    dim3 grid((pmax + BLOCK * APT - 1) / (BLOCK * APT), SPLIT, 2);
    min_kernel<<<grid, BLOCK>>>(n, m);

    reduce_kernel<<<64, 256>>>(n, m, out);
}

// round 7
// speedup vs baseline: 1.2457x; 1.2457x over previous
#include <cuda_runtime.h>
#include <cstdint>

// ---------------------------------------------------------------------------
// ChamferLoss fused: compute each pairwise d^2 ONCE, serve both directions.
//   d^2(i,j) = fma(ax,-2bx, fma(ay,-2by, fma(az,-2bz, sq_b))) + sq_a
// Rows i = target points (row-min -> g_min[0]); cols j = output points
// (col-min -> g_min[1]).  4 fma-pipe ops per element vs 6 for two passes.
// ---------------------------------------------------------------------------

#define NMAX   16384
#define BLOCK  128
#define RPT    8                    // rows per thread
#define TROWS  (BLOCK * RPT)        // 1024 rows per block
#define TCOLS  256                  // ref points per block (4KB smem)

// scratch (no device allocations allowed)
__device__ float4   g_row[NMAX];    // target: (x, y, z, sq)
__device__ float4   g_col[NMAX];    // output: (-2x, -2y, -2z, sq)
__device__ unsigned g_min[2][NMAX]; // [0]: per-target min, [1]: per-output min

// ---------------------------------------------------------------------------
__global__ void prep_kernel(const float* __restrict__ tgt,
                            const float* __restrict__ outp,
                            int n, int m, float* out) {
    int i = blockIdx.x * blockDim.x + threadIdx.x;
    if (i == 0) *out = 0.0f;
    if (i < n) {
        float x = tgt[3 * i], y = tgt[3 * i + 1], z = tgt[3 * i + 2];
        float sq = fmaf(x, x, fmaf(y, y, z * z));
        g_row[i] = make_float4(x, y, z, sq);
        g_min[0][i] = 0x7F800000u;           // +inf
    }
    if (i < m) {
        float x = outp[3 * i], y = outp[3 * i + 1], z = outp[3 * i + 2];
        float sq = fmaf(x, x, fmaf(y, y, z * z));
        g_col[i] = make_float4(-2.0f * x, -2.0f * y, -2.0f * z, sq);
        g_min[1][i] = 0x7F800000u;
    }
}

// ---------------------------------------------------------------------------
__global__ __launch_bounds__(BLOCK) void min_kernel(int n, int m) {
    __shared__ float4   sh[TCOLS];       // ref slice (output pts, premul -2)
    __shared__ unsigned colmin[TCOLS];   // block-local col mins (uint bits)

    const int rbase = blockIdx.y * TCOLS;
    const int L = min(TCOLS, m - rbase);

    for (int j = threadIdx.x; j < TCOLS; j += BLOCK) {
        sh[j] = (j < L) ? g_col[rbase + j]
                        : make_float4(0.f, 0.f, 0.f, __uint_as_float(0x7F800000u));
        colmin[j] = 0x7F800000u;
    }
    __syncthreads();

    // load RPT target rows into registers
    const int qbase = blockIdx.x * TROWS;
    float ax[RPT], ay[RPT], az[RPT], sqa[RPT], rmin[RPT];
    int qidx[RPT];
    #pragma unroll
    for (int k = 0; k < RPT; k++) {
        int idx = qbase + threadIdx.x + k * BLOCK;
        qidx[k] = idx;
        float4 q;
        if (idx < n) q = g_row[idx];
        else         q = make_float4(0.f, 0.f, 0.f, __uint_as_float(0x7F800000u));
        ax[k] = q.x; ay[k] = q.y; az[k] = q.z; sqa[k] = q.w;
        rmin[k] = __uint_as_float(0x7F800000u);
    }

    // main loop: per (row, col): 3 FFMA + 1 FADD (fma pipe) + FMNMX (alu)
    #pragma unroll 2
    for (int j = 0; j < TCOLS; j++) {
        float4 b = sh[j];            // broadcast LDS.128
        float d2[RPT];
        #pragma unroll
        for (int k = 0; k < RPT; k++) {
            float t = fmaf(az[k], b.z, b.w);
            t = fmaf(ay[k], b.y, t);
            t = fmaf(ax[k], b.x, t);
            d2[k] = t + sqa[k];                     // full d^2 for col path
            rmin[k] = fminf(rmin[k], d2[k]);        // row path
        }
        // thread-local min tree over RPT rows, then one shared atomicMin
        float c01 = fminf(d2[0], d2[1]), c23 = fminf(d2[2], d2[3]);
        float c45 = fminf(d2[4], d2[5]), c67 = fminf(d2[6], d2[7]);
        float c = fminf(fminf(c01, c23), fminf(c45, c67));
        atomicMin(&colmin[j], __float_as_uint(fmaxf(c, 0.0f)));
    }

    // publish row mins
    #pragma unroll
    for (int k = 0; k < RPT; k++) {
        if (qidx[k] < n) {
            float v = fmaxf(rmin[k], 0.0f);
            atomicMin(&g_min[0][qidx[k]], __float_as_uint(v));
        }
    }
    __syncthreads();

    // publish col mins
    for (int j = threadIdx.x; j < L; j += BLOCK)
        atomicMin(&g_min[1][rbase + j], colmin[j]);
}

// ---------------------------------------------------------------------------
__global__ void reduce_kernel(int n, int m, float* out) {
    __shared__ float warp_sums[8];
    const int total = n + m;
    float s = 0.0f;
    for (int i = blockIdx.x * blockDim.x + threadIdx.x; i < total;
         i += gridDim.x * blockDim.x) {
        unsigned u = (i < n) ? g_min[0][i] : g_min[1][i - n];
        s += sqrtf(__uint_as_float(u));
    }
    #pragma unroll
    for (int o = 16; o > 0; o >>= 1)
        s += __shfl_down_sync(0xFFFFFFFFu, s, o);
    int lane = threadIdx.x & 31, wid = threadIdx.x >> 5;
    if (lane == 0) warp_sums[wid] = s;
    __syncthreads();
    if (wid == 0) {
        s = (lane < (int)(blockDim.x / 32)) ? warp_sums[lane] : 0.0f;
        #pragma unroll
        for (int o = 16; o > 0; o >>= 1)
            s += __shfl_down_sync(0xFFFFFFFFu, s, o);
        if (lane == 0) atomicAdd(out, s * 1.0e-3f);
    }
}

// ---------------------------------------------------------------------------
extern "C" void kernel_launch(void* const* d_in, const int* in_sizes, int n_in,
                              void* d_out, int out_size) {
    const float* target = (const float*)d_in[0];
    const float* output = (const float*)d_in[1];
    const int n = in_sizes[0] / 3;   // target points (rows)
    const int m = in_sizes[1] / 3;   // output points (cols)
    float* out = (float*)d_out;

    int pmax = max(n, m);
    prep_kernel<<<(pmax + 255) / 256, 256>>>(target, output, n, m, out);

    dim3 grid((n + TROWS - 1) / TROWS, (m + TCOLS - 1) / TCOLS);
    min_kernel<<<grid, BLOCK>>>(n, m);

    reduce_kernel<<<64, 256>>>(n, m, out);
}